// round 6
// baseline (speedup 1.0000x reference)
#include <cuda_runtime.h>
#include <cuda_bf16.h>
#include <cstdint>

// Problem constants
#define BSZ   128
#define CDIM  2048
#define HW    196          // 14*14
#define NDESC 32
#define NANS  1845
#define CD4   (CDIM / 4)   // 512 float4 per attended row

// GEMM tiling
#define TS    8            // samples per chunk (one W pass covers count<=8)
#define TA    3            // answers per warp
#define NWARP 12
#define NTHR  384
#define APB   (NWARP * TA) // 36 answers per block

typedef unsigned long long ull;

// Scratch (no allocations allowed)
__device__ float g_att[BSZ * CDIM];      // attended [B, C]
__device__ int   g_cnt[NDESC];           // samples per descriptor
__device__ int   g_list[NDESC * BSZ];    // sample ids per descriptor

// ---------------------------------------------------------------------------
// packed f32x2 helpers (ptxas never emits FFMA2 from C++ — PTX only)
// ---------------------------------------------------------------------------
__device__ __forceinline__ ull fma2(ull a, ull b, ull c) {
    ull r;
    asm("fma.rn.f32x2 %0, %1, %2, %3;" : "=l"(r) : "l"(a), "l"(b), "l"(c));
    return r;
}
__device__ __forceinline__ ull add2(ull a, ull b) {
    ull r;
    asm("add.rn.f32x2 %0, %1, %2;" : "=l"(r) : "l"(a), "l"(b));
    return r;
}

// ---------------------------------------------------------------------------
// Kernel A: attended[b,c] = (1/196) * sum_hw mask[b,hw] * feat[b,c,hw]
// grid (32, 128), block 256. Warp processes 4 channels/iter (8 LDG.128 in
// flight). Block (0,0) also builds the grouping tables.
// ---------------------------------------------------------------------------
__global__ void __launch_bounds__(256)
attend_kernel(const float* __restrict__ mask,
              const float* __restrict__ feat,
              const int* __restrict__ inst32) {
    __shared__ float4 smask[49];
    const int b   = blockIdx.y;
    const int tid = threadIdx.x;

    const float4* mrow = reinterpret_cast<const float4*>(mask + (size_t)b * HW);
    if (tid < 49) smask[tid] = mrow[tid];
    __syncthreads();

    const int warp = tid >> 5;
    const int lane = tid & 31;

    #pragma unroll
    for (int it = 0; it < 2; ++it) {
        const int c0 = blockIdx.x * 64 + it * 32 + warp * 4;   // 4-aligned
        const float4* fr[4];
        #pragma unroll
        for (int j = 0; j < 4; ++j)
            fr[j] = reinterpret_cast<const float4*>(
                        feat + ((size_t)b * CDIM + c0 + j) * HW);

        float4 fa[4], fb[4];
        #pragma unroll
        for (int j = 0; j < 4; ++j) fa[j] = fr[j][lane];
        if (lane < 17) {
            #pragma unroll
            for (int j = 0; j < 4; ++j) fb[j] = fr[j][lane + 32];
        }

        float s[4];
        float4 ma = smask[lane];
        #pragma unroll
        for (int j = 0; j < 4; ++j)
            s[j] = fa[j].x * ma.x + fa[j].y * ma.y + fa[j].z * ma.z + fa[j].w * ma.w;
        if (lane < 17) {
            float4 mb = smask[lane + 32];
            #pragma unroll
            for (int j = 0; j < 4; ++j)
                s[j] += fb[j].x * mb.x + fb[j].y * mb.y + fb[j].z * mb.z + fb[j].w * mb.w;
        }
        #pragma unroll
        for (int j = 0; j < 4; ++j)
            #pragma unroll
            for (int off = 16; off > 0; off >>= 1)
                s[j] += __shfl_xor_sync(0xffffffffu, s[j], off);

        if (lane == 0) {
            float4 o = make_float4(s[0] * (1.0f / HW), s[1] * (1.0f / HW),
                                   s[2] * (1.0f / HW), s[3] * (1.0f / HW));
            reinterpret_cast<float4*>(g_att)[((size_t)b * CDIM + c0) >> 2] = o;
        }
    }

    // ---- grouping tables, computed once by block (0,0) ----
    if (blockIdx.x == 0 && blockIdx.y == 0) {
        __shared__ int sh_inst[BSZ];
        __shared__ int sh_flag;
        if (tid == 0) sh_flag = 0;
        __syncthreads();
        if (tid < 64) {
            // int64 little-endian => odd 32-bit words of first 64 entries are 0
            if (inst32[2 * tid + 1] != 0) atomicOr(&sh_flag, 1);
        }
        __syncthreads();
        const bool is64 = (sh_flag == 0);
        if (tid < BSZ) sh_inst[tid] = is64 ? inst32[2 * tid] : inst32[tid];
        __syncthreads();
        if (tid == 0) {
            int cnt[NDESC];
            #pragma unroll
            for (int dd = 0; dd < NDESC; ++dd) cnt[dd] = 0;
            for (int bb = 0; bb < BSZ; ++bb) {
                int dd = sh_inst[bb];
                g_list[dd * BSZ + cnt[dd]++] = bb;
            }
            #pragma unroll
            for (int dd = 0; dd < NDESC; ++dd) g_cnt[dd] = cnt[dd];
        }
    }
}

// ---------------------------------------------------------------------------
// Kernel B: grouped GEMM, channel-packed f32x2, W register stream.
// preds[s,a] = sum_c att[s,c] * W[d,a,c] + bias[d,a]
// grid (52, 32). 384 threads = 12 warps. Warp tile: 3 answers x 8 samples.
// Accumulators hold (even-ch, odd-ch) f32x2 partials; butterfly + lo+hi add
// finish the K reduction. One W pass for count<=8 (no chunk re-reads).
// ---------------------------------------------------------------------------
__global__ void __launch_bounds__(NTHR, 2)
gemm_kernel(const float* __restrict__ Wm,
            const float* __restrict__ bias,
            float* __restrict__ out) {
    const int d     = blockIdx.y;
    const int count = g_cnt[d];
    if (count == 0) return;

    extern __shared__ float att_smem[];    // [TS][CDIM] floats = 64 KB
    __shared__ int s_b[TS];

    const int tid  = threadIdx.x;
    const int warp = tid >> 5;
    const int lane = tid & 31;
    const int aw   = blockIdx.x * APB + warp * TA;

    // W viewed as ulonglong2: one LDG.128 = 4 channels = 2 packed f32x2
    const ulonglong2* __restrict__ W2 =
        reinterpret_cast<const ulonglong2*>(Wm);
    unsigned wrow[TA];
    #pragma unroll
    for (int ta = 0; ta < TA; ++ta) {
        int a = aw + ta; if (a >= NANS) a = NANS - 1;   // clamp; stores guarded
        wrow[ta] = (unsigned)((d * NANS + a) * CD4);
    }

    const float4* __restrict__ gatt4 = reinterpret_cast<const float4*>(g_att);
    const ulonglong2* __restrict__ A2 =
        reinterpret_cast<const ulonglong2*>(att_smem);

    const int nchunks = (count + TS - 1) / TS;

    for (int sc = 0; sc < nchunks; ++sc) {
        if (tid < TS) {
            int si = sc * TS + tid;
            s_b[tid] = (si < count) ? g_list[d * BSZ + si] : -1;
        }
        __syncthreads();
        // stage attended tile [TS][2048] (zeros for padding slots)
        for (int i = tid; i < TS * CD4; i += NTHR) {
            int ts = i >> 9;
            int c4 = i & (CD4 - 1);
            int bb = s_b[ts];
            float4 v = make_float4(0.f, 0.f, 0.f, 0.f);
            if (bb >= 0) v = gatt4[(size_t)bb * CD4 + c4];
            reinterpret_cast<float4*>(att_smem)[i] = v;
        }
        __syncthreads();

        ull acc[TA][TS];
        #pragma unroll
        for (int ta = 0; ta < TA; ++ta)
            #pragma unroll
            for (int ts = 0; ts < TS; ++ts) acc[ta][ts] = 0ull;

        // K loop: 512 float4 positions, warp-stride 32 -> 16 iters
        #pragma unroll
        for (int it = 0; it < CD4 / 32; ++it) {
            const int cc = it * 32 + lane;
            ulonglong2 w[TA];
            #pragma unroll
            for (int ta = 0; ta < TA; ++ta) w[ta] = W2[wrow[ta] + cc];
            #pragma unroll
            for (int ts = 0; ts < TS; ++ts) {
                ulonglong2 av = A2[ts * CD4 + cc];
                #pragma unroll
                for (int ta = 0; ta < TA; ++ta) {
                    acc[ta][ts] = fma2(w[ta].x, av.x, acc[ta][ts]);
                    acc[ta][ts] = fma2(w[ta].y, av.y, acc[ta][ts]);
                }
            }
        }

        // butterfly reduce packed accs: every lane ends with full sums
        #pragma unroll
        for (int ta = 0; ta < TA; ++ta)
            #pragma unroll
            for (int ts = 0; ts < TS; ++ts)
                #pragma unroll
                for (int off = 16; off > 0; off >>= 1)
                    acc[ta][ts] = add2(acc[ta][ts],
                        __shfl_xor_sync(0xffffffffu, acc[ta][ts], off));

        // lane l (<24) stores pair (ta = l/8, ts = l%8); lo+hi finishes K sum
        if (lane < TA * TS) {
            int ta = lane >> 3;
            int ts = lane & 7;
            int a  = aw + ta;
            int bb = s_b[ts];
            if (a < NANS && bb >= 0) {
                ull v = acc[ta][ts];
                float lo = __uint_as_float((unsigned)(v & 0xffffffffull));
                float hi = __uint_as_float((unsigned)(v >> 32));
                out[(size_t)bb * NANS + a] = lo + hi + bias[(size_t)d * NANS + a];
            }
        }
        __syncthreads();   // protect s_b / att_smem before next chunk rewrites
    }
}

// ---------------------------------------------------------------------------
extern "C" void kernel_launch(void* const* d_in, const int* in_sizes, int n_in,
                              void* d_out, int out_size) {
    const float* mask = (const float*)d_in[0];   // [B,1,14,14]
    const float* feat = (const float*)d_in[1];   // [B,C,14,14]
    const int*   inst = (const int*)d_in[2];     // [B] int64 or int32
    const float* Wm   = (const float*)d_in[3];   // [32,1845,2048]
    const float* bias = (const float*)d_in[4];   // [32,1845]
    float* out = (float*)d_out;                  // [B,1845]

    static const size_t GEMM_SMEM = TS * CDIM * sizeof(float);   // 64 KB
    cudaFuncSetAttribute(gemm_kernel,
                         cudaFuncAttributeMaxDynamicSharedMemorySize,
                         (int)GEMM_SMEM);

    attend_kernel<<<dim3(32, 128), 256>>>(mask, feat, inst);
    gemm_kernel<<<dim3((NANS + APB - 1) / APB, NDESC), NTHR, GEMM_SMEM>>>(Wm, bias, out);
}

// round 7
// speedup vs baseline: 1.0346x; 1.0346x over previous
#include <cuda_runtime.h>
#include <cuda_bf16.h>
#include <cstdint>

// Problem constants
#define BSZ   128
#define CDIM  2048
#define HW    196          // 14*14
#define NDESC 32
#define NANS  1845
#define CD4   (CDIM / 4)   // 512 float4 per attended row

#define TSAMP 4            // samples per chunk
typedef unsigned long long ull;

// Scratch (no allocations allowed)
__device__ float g_att[BSZ * CDIM];      // attended [B, C]
__device__ int   g_cnt[NDESC];           // samples per descriptor
__device__ int   g_list[NDESC * BSZ];    // sample ids per descriptor

// ---------------------------------------------------------------------------
// packed f32x2 helpers (ptxas never emits FFMA2 from C++ — PTX only)
// ---------------------------------------------------------------------------
__device__ __forceinline__ ull fma2(ull a, ull b, ull c) {
    ull r;
    asm("fma.rn.f32x2 %0, %1, %2, %3;" : "=l"(r) : "l"(a), "l"(b), "l"(c));
    return r;
}
__device__ __forceinline__ ull add2(ull a, ull b) {
    ull r;
    asm("add.rn.f32x2 %0, %1, %2;" : "=l"(r) : "l"(a), "l"(b));
    return r;
}

// ---------------------------------------------------------------------------
// Kernel A: attended[b,c] = (1/196) * sum_hw mask[b,hw] * feat[b,c,hw]
// grid (32, 128), block 256. Warp processes 4 channels/iter (8 LDG.128 in
// flight). Block (0,0) also builds the grouping tables.
// ---------------------------------------------------------------------------
__global__ void __launch_bounds__(256)
attend_kernel(const float* __restrict__ mask,
              const float* __restrict__ feat,
              const int* __restrict__ inst32) {
    __shared__ float4 smask[49];
    const int b   = blockIdx.y;
    const int tid = threadIdx.x;

    const float4* mrow = reinterpret_cast<const float4*>(mask + (size_t)b * HW);
    if (tid < 49) smask[tid] = mrow[tid];
    __syncthreads();

    const int warp = tid >> 5;
    const int lane = tid & 31;

    #pragma unroll
    for (int it = 0; it < 2; ++it) {
        const int c0 = blockIdx.x * 64 + it * 32 + warp * 4;   // 4-aligned
        const float4* fr[4];
        #pragma unroll
        for (int j = 0; j < 4; ++j)
            fr[j] = reinterpret_cast<const float4*>(
                        feat + ((size_t)b * CDIM + c0 + j) * HW);

        float4 fa[4], fb[4];
        #pragma unroll
        for (int j = 0; j < 4; ++j) fa[j] = fr[j][lane];
        if (lane < 17) {
            #pragma unroll
            for (int j = 0; j < 4; ++j) fb[j] = fr[j][lane + 32];
        }

        float s[4];
        float4 ma = smask[lane];
        #pragma unroll
        for (int j = 0; j < 4; ++j)
            s[j] = fa[j].x * ma.x + fa[j].y * ma.y + fa[j].z * ma.z + fa[j].w * ma.w;
        if (lane < 17) {
            float4 mb = smask[lane + 32];
            #pragma unroll
            for (int j = 0; j < 4; ++j)
                s[j] += fb[j].x * mb.x + fb[j].y * mb.y + fb[j].z * mb.z + fb[j].w * mb.w;
        }
        #pragma unroll
        for (int j = 0; j < 4; ++j)
            #pragma unroll
            for (int off = 16; off > 0; off >>= 1)
                s[j] += __shfl_xor_sync(0xffffffffu, s[j], off);

        if (lane == 0) {
            float4 o = make_float4(s[0] * (1.0f / HW), s[1] * (1.0f / HW),
                                   s[2] * (1.0f / HW), s[3] * (1.0f / HW));
            reinterpret_cast<float4*>(g_att)[((size_t)b * CDIM + c0) >> 2] = o;
        }
    }

    // ---- grouping tables, computed once by block (0,0) ----
    if (blockIdx.x == 0 && blockIdx.y == 0) {
        __shared__ int sh_inst[BSZ];
        __shared__ int sh_flag;
        if (tid == 0) sh_flag = 0;
        __syncthreads();
        if (tid < 64) {
            // int64 little-endian => odd 32-bit words of first 64 entries are 0
            if (inst32[2 * tid + 1] != 0) atomicOr(&sh_flag, 1);
        }
        __syncthreads();
        const bool is64 = (sh_flag == 0);
        if (tid < BSZ) sh_inst[tid] = is64 ? inst32[2 * tid] : inst32[tid];
        __syncthreads();
        if (tid == 0) {
            int cnt[NDESC];
            #pragma unroll
            for (int dd = 0; dd < NDESC; ++dd) cnt[dd] = 0;
            for (int bb = 0; bb < BSZ; ++bb) {
                int dd = sh_inst[bb];
                g_list[dd * BSZ + cnt[dd]++] = bb;
            }
            #pragma unroll
            for (int dd = 0; dd < NDESC; ++dd) g_cnt[dd] = cnt[dd];
        }
    }
}

// ---------------------------------------------------------------------------
// Kernel B: grouped GEMM — R3 shape (TA=4 x TS=4, 8 warps, 3 blocks/SM,
// W register stream batched 2 columns) with packed f32x2 FMA math.
// preds[s,a] = sum_c att[s,c] * W[d,a,c] + bias[d,a]
// grid (58, 32). Accumulators hold (even-ch, odd-ch) f32x2 partials;
// butterfly + lo+hi add finish the K reduction.
// ---------------------------------------------------------------------------
__global__ void __launch_bounds__(256, 3)
gemm_kernel(const float* __restrict__ Wm,
            const float* __restrict__ bias,
            float* __restrict__ out) {
    const int d     = blockIdx.y;
    const int count = g_cnt[d];
    if (count == 0) return;

    const int tid  = threadIdx.x;
    const int warp = tid >> 5;
    const int lane = tid & 31;

    __shared__ float4 s_att[TSAMP][CD4];   // 32 KB
    __shared__ int    s_b[TSAMP];

    const int aw = blockIdx.x * 32 + warp * 4;   // first of 4 answers
    const ulonglong2* __restrict__ W2 = reinterpret_cast<const ulonglong2*>(Wm);
    unsigned wrow[4];
    #pragma unroll
    for (int ta = 0; ta < 4; ++ta) {
        int a = aw + ta; if (a >= NANS) a = NANS - 1;   // clamp; stores guarded
        wrow[ta] = (unsigned)((d * NANS + a) * CD4);
    }
    const float4* __restrict__ gatt4 = reinterpret_cast<const float4*>(g_att);
    const ulonglong2* __restrict__ A2 =
        reinterpret_cast<const ulonglong2*>(&s_att[0][0]);

    const int nchunks = (count + TSAMP - 1) / TSAMP;

    for (int sc = 0; sc < nchunks; ++sc) {
        if (tid < TSAMP) {
            int si = sc * TSAMP + tid;
            s_b[tid] = (si < count) ? g_list[d * BSZ + si] : -1;
        }
        __syncthreads();
        // stage attended tile (full K), zeros for padding samples
        for (int i = tid; i < TSAMP * CD4; i += 256) {
            int ts = i >> 9;            // / CD4
            int cc = i & (CD4 - 1);
            int bb = s_b[ts];
            float4 v = make_float4(0.f, 0.f, 0.f, 0.f);
            if (bb >= 0) v = gatt4[(size_t)bb * CD4 + cc];
            s_att[ts][cc] = v;
        }
        __syncthreads();

        ull acc[4][TSAMP];
        #pragma unroll
        for (int ta = 0; ta < 4; ++ta)
            #pragma unroll
            for (int ts = 0; ts < TSAMP; ++ts) acc[ta][ts] = 0ull;

        // K loop: 512 float4 columns / 32 lanes = 16 iters, batched by 2
        #pragma unroll
        for (int it = 0; it < CD4 / 32; it += 2) {
            const int cc0 = it * 32 + lane;
            const int cc1 = cc0 + 32;
            ulonglong2 w[2][4];
            #pragma unroll
            for (int ta = 0; ta < 4; ++ta) w[0][ta] = __ldcs(&W2[wrow[ta] + cc0]);
            #pragma unroll
            for (int ta = 0; ta < 4; ++ta) w[1][ta] = __ldcs(&W2[wrow[ta] + cc1]);

            #pragma unroll
            for (int h = 0; h < 2; ++h) {
                const int cc = it * 32 + h * 32 + lane;
                #pragma unroll
                for (int ts = 0; ts < TSAMP; ++ts) {
                    ulonglong2 av = A2[ts * CD4 + cc];
                    #pragma unroll
                    for (int ta = 0; ta < 4; ++ta) {
                        acc[ta][ts] = fma2(w[h][ta].x, av.x, acc[ta][ts]);
                        acc[ta][ts] = fma2(w[h][ta].y, av.y, acc[ta][ts]);
                    }
                }
            }
        }

        // butterfly reduce packed accs: every lane ends with full sums
        #pragma unroll
        for (int ta = 0; ta < 4; ++ta)
            #pragma unroll
            for (int ts = 0; ts < TSAMP; ++ts)
                #pragma unroll
                for (int off = 16; off > 0; off >>= 1)
                    acc[ta][ts] = add2(acc[ta][ts],
                        __shfl_xor_sync(0xffffffffu, acc[ta][ts], off));

        // lane l (<16) stores pair (ta = l/4, ts = l%4); lo+hi finishes K sum
        if (lane < 16) {
            int ta = lane >> 2;
            int ts = lane & 3;
            int a  = aw + ta;
            int bb = s_b[ts];
            if (a < NANS && bb >= 0) {
                ull v = acc[ta][ts];
                float lo = __uint_as_float((unsigned)(v & 0xffffffffull));
                float hi = __uint_as_float((unsigned)(v >> 32));
                out[(size_t)bb * NANS + a] = lo + hi + bias[(size_t)d * NANS + a];
            }
        }
        __syncthreads();   // protect s_b / s_att before next chunk rewrites
    }
}

// ---------------------------------------------------------------------------
extern "C" void kernel_launch(void* const* d_in, const int* in_sizes, int n_in,
                              void* d_out, int out_size) {
    const float* mask = (const float*)d_in[0];   // [B,1,14,14]
    const float* feat = (const float*)d_in[1];   // [B,C,14,14]
    const int*   inst = (const int*)d_in[2];     // [B] int64 or int32
    const float* Wm   = (const float*)d_in[3];   // [32,1845,2048]
    const float* bias = (const float*)d_in[4];   // [32,1845]
    float* out = (float*)d_out;                  // [B,1845]

    attend_kernel<<<dim3(32, 128), 256>>>(mask, feat, inst);
    gemm_kernel<<<dim3((NANS + 31) / 32, NDESC), 256>>>(Wm, bias, out);
}

// round 8
// speedup vs baseline: 1.2217x; 1.1808x over previous
#include <cuda_runtime.h>
#include <cuda_bf16.h>
#include <cstdint>

// Problem constants
#define BSZ   128
#define CDIM  2048
#define HW    196          // 14*14
#define NDESC 32
#define NANS  1845
#define CD4   (CDIM / 4)   // 512 float4 per attended row

#define TSAMP 8            // samples per chunk: one W pass for count<=8

// Scratch (no allocations allowed)
__device__ float g_att[BSZ * CDIM];      // attended [B, C]
__device__ int   g_cnt[NDESC];           // samples per descriptor
__device__ int   g_list[NDESC * BSZ];    // sample ids per descriptor

// ---------------------------------------------------------------------------
// Kernel A: attended[b,c] = (1/196) * sum_hw mask[b,hw] * feat[b,c,hw]
// grid (32, 128), block 256. Warp processes 4 channels/iter (8 LDG.128 in
// flight). Block (0,0) also builds the grouping tables.
// ---------------------------------------------------------------------------
__global__ void __launch_bounds__(256)
attend_kernel(const float* __restrict__ mask,
              const float* __restrict__ feat,
              const int* __restrict__ inst32) {
    __shared__ float4 smask[49];
    const int b   = blockIdx.y;
    const int tid = threadIdx.x;

    const float4* mrow = reinterpret_cast<const float4*>(mask + (size_t)b * HW);
    if (tid < 49) smask[tid] = mrow[tid];
    __syncthreads();

    const int warp = tid >> 5;
    const int lane = tid & 31;

    #pragma unroll
    for (int it = 0; it < 2; ++it) {
        const int c0 = blockIdx.x * 64 + it * 32 + warp * 4;   // 4-aligned
        const float4* fr[4];
        #pragma unroll
        for (int j = 0; j < 4; ++j)
            fr[j] = reinterpret_cast<const float4*>(
                        feat + ((size_t)b * CDIM + c0 + j) * HW);

        float4 fa[4], fb[4];
        #pragma unroll
        for (int j = 0; j < 4; ++j) fa[j] = fr[j][lane];
        if (lane < 17) {
            #pragma unroll
            for (int j = 0; j < 4; ++j) fb[j] = fr[j][lane + 32];
        }

        float s[4];
        float4 ma = smask[lane];
        #pragma unroll
        for (int j = 0; j < 4; ++j)
            s[j] = fa[j].x * ma.x + fa[j].y * ma.y + fa[j].z * ma.z + fa[j].w * ma.w;
        if (lane < 17) {
            float4 mb = smask[lane + 32];
            #pragma unroll
            for (int j = 0; j < 4; ++j)
                s[j] += fb[j].x * mb.x + fb[j].y * mb.y + fb[j].z * mb.z + fb[j].w * mb.w;
        }
        #pragma unroll
        for (int j = 0; j < 4; ++j)
            #pragma unroll
            for (int off = 16; off > 0; off >>= 1)
                s[j] += __shfl_xor_sync(0xffffffffu, s[j], off);

        if (lane == 0) {
            float4 o = make_float4(s[0] * (1.0f / HW), s[1] * (1.0f / HW),
                                   s[2] * (1.0f / HW), s[3] * (1.0f / HW));
            reinterpret_cast<float4*>(g_att)[((size_t)b * CDIM + c0) >> 2] = o;
        }
    }

    // ---- grouping tables, computed once by block (0,0) ----
    if (blockIdx.x == 0 && blockIdx.y == 0) {
        __shared__ int sh_inst[BSZ];
        __shared__ int sh_flag;
        if (tid == 0) sh_flag = 0;
        __syncthreads();
        if (tid < 64) {
            // int64 little-endian => odd 32-bit words of first 64 entries are 0
            if (inst32[2 * tid + 1] != 0) atomicOr(&sh_flag, 1);
        }
        __syncthreads();
        const bool is64 = (sh_flag == 0);
        if (tid < BSZ) sh_inst[tid] = is64 ? inst32[2 * tid] : inst32[tid];
        __syncthreads();
        if (tid == 0) {
            int cnt[NDESC];
            #pragma unroll
            for (int dd = 0; dd < NDESC; ++dd) cnt[dd] = 0;
            for (int bb = 0; bb < BSZ; ++bb) {
                int dd = sh_inst[bb];
                g_list[dd * BSZ + cnt[dd]++] = bb;
            }
            #pragma unroll
            for (int dd = 0; dd < NDESC; ++dd) g_cnt[dd] = cnt[dd];
        }
    }
}

// ---------------------------------------------------------------------------
// Kernel B: grouped GEMM — R3 shape (8 warps, TA=4, batch-2 W register
// stream, 3 blocks/SM) with TS=8 (single W pass for count<=8) and
// streaming (__ldcs) W loads so g_att stays L2-resident.
// preds[s,a] = sum_c att[s,c] * W[d,a,c] + bias[d,a].  grid (58, 32).
// ---------------------------------------------------------------------------
__global__ void __launch_bounds__(256, 3)
gemm_kernel(const float* __restrict__ Wm,
            const float* __restrict__ bias,
            float* __restrict__ out) {
    const int d     = blockIdx.y;
    const int count = g_cnt[d];
    if (count == 0) return;

    extern __shared__ float4 s_att[];      // [TSAMP][CD4] = 64 KB
    __shared__ int s_b[TSAMP];

    const int tid  = threadIdx.x;
    const int warp = tid >> 5;
    const int lane = tid & 31;

    const int aw = blockIdx.x * 32 + warp * 4;   // first of 4 answers
    const float4* __restrict__ W4 = reinterpret_cast<const float4*>(Wm);
    unsigned wrow[4];
    #pragma unroll
    for (int ta = 0; ta < 4; ++ta) {
        int a = aw + ta; if (a >= NANS) a = NANS - 1;   // clamp; stores guarded
        wrow[ta] = (unsigned)((d * NANS + a) * CD4);
    }
    const float4* __restrict__ gatt4 = reinterpret_cast<const float4*>(g_att);

    const int nchunks = (count + TSAMP - 1) / TSAMP;   // ==1 for ~98% of d

    for (int sc = 0; sc < nchunks; ++sc) {
        if (tid < TSAMP) {
            int si = sc * TSAMP + tid;
            s_b[tid] = (si < count) ? g_list[d * BSZ + si] : -1;
        }
        __syncthreads();
        // stage attended tile (full K), zeros for padding samples (L2 hits)
        for (int i = tid; i < TSAMP * CD4; i += 256) {
            int ts = i >> 9;            // / CD4
            int cc = i & (CD4 - 1);
            int bb = s_b[ts];
            float4 v = make_float4(0.f, 0.f, 0.f, 0.f);
            if (bb >= 0) v = gatt4[(size_t)bb * CD4 + cc];
            s_att[i] = v;
        }
        __syncthreads();

        float acc[4][TSAMP];
        #pragma unroll
        for (int ta = 0; ta < 4; ++ta)
            #pragma unroll
            for (int ts = 0; ts < TSAMP; ++ts) acc[ta][ts] = 0.0f;

        // K loop: 512 float4 columns / 32 lanes = 16 iters, batched by 2
        #pragma unroll
        for (int it = 0; it < CD4 / 32; it += 2) {
            const int cc0 = it * 32 + lane;
            const int cc1 = cc0 + 32;
            float4 w[2][4];
            #pragma unroll
            for (int ta = 0; ta < 4; ++ta) w[0][ta] = __ldcs(&W4[wrow[ta] + cc0]);
            #pragma unroll
            for (int ta = 0; ta < 4; ++ta) w[1][ta] = __ldcs(&W4[wrow[ta] + cc1]);

            #pragma unroll
            for (int h = 0; h < 2; ++h) {
                const int cc = it * 32 + h * 32 + lane;
                #pragma unroll
                for (int ts = 0; ts < TSAMP; ++ts) {
                    float4 av = s_att[ts * CD4 + cc];
                    #pragma unroll
                    for (int ta = 0; ta < 4; ++ta) {
                        acc[ta][ts] += w[h][ta].x * av.x;
                        acc[ta][ts] += w[h][ta].y * av.y;
                        acc[ta][ts] += w[h][ta].z * av.z;
                        acc[ta][ts] += w[h][ta].w * av.w;
                    }
                }
            }
        }

        // butterfly reduce: every lane ends with full sums
        #pragma unroll
        for (int ta = 0; ta < 4; ++ta)
            #pragma unroll
            for (int ts = 0; ts < TSAMP; ++ts)
                #pragma unroll
                for (int off = 16; off > 0; off >>= 1)
                    acc[ta][ts] += __shfl_xor_sync(0xffffffffu, acc[ta][ts], off);

        // lane l stores pair (ta = l/8, ts = l%8) — exact 32-way mapping
        {
            int ta = lane >> 3;
            int ts = lane & 7;
            int a  = aw + ta;
            int bb = s_b[ts];
            if (a < NANS && bb >= 0)
                out[(size_t)bb * NANS + a] = acc[ta][ts] + bias[(size_t)d * NANS + a];
        }
        __syncthreads();   // protect s_b / s_att before next chunk rewrites
    }
}

// ---------------------------------------------------------------------------
extern "C" void kernel_launch(void* const* d_in, const int* in_sizes, int n_in,
                              void* d_out, int out_size) {
    const float* mask = (const float*)d_in[0];   // [B,1,14,14]
    const float* feat = (const float*)d_in[1];   // [B,C,14,14]
    const int*   inst = (const int*)d_in[2];     // [B] int64 or int32
    const float* Wm   = (const float*)d_in[3];   // [32,1845,2048]
    const float* bias = (const float*)d_in[4];   // [32,1845]
    float* out = (float*)d_out;                  // [B,1845]

    static const size_t GEMM_SMEM = TSAMP * CDIM * sizeof(float);   // 64 KB
    cudaFuncSetAttribute(gemm_kernel,
                         cudaFuncAttributeMaxDynamicSharedMemorySize,
                         (int)GEMM_SMEM);

    attend_kernel<<<dim3(32, 128), 256>>>(mask, feat, inst);
    gemm_kernel<<<dim3((NANS + 31) / 32, NDESC), 256, GEMM_SMEM>>>(Wm, bias, out);
}